// round 5
// baseline (speedup 1.0000x reference)
#include <cuda_runtime.h>
#include <cuda_fp16.h>
#include <cstdint>

// ConvexSampler R5: prep kernel (copy head + fp16 table + all labels, one z pass)
// then a pure convex gather-blend kernel.
// Inputs (metadata order):
//   d_in[0] z         float32 [8192*768]
//   d_in[1] label_ids int32   [8192]
//   d_in[2] idx_i     int32   [32768]
//   d_in[3] idx_j     int32   [32768]
//   d_in[4] s         float32 [32768]
// Output (flattened tuple, float32):
//   [0 .. 40960*768)        z_out (first 8192 rows = z exact copy, next 32768 = convex)
//   [40960*768 .. +40960)   labels (first 8192 = label_ids as float, rest = 150)

#define BATCH        8192
#define FEAT_DIM     768
#define NUM_CONVEX   32768
#define TOTAL_ROWS   (BATCH + NUM_CONVEX)
#define F4_PER_ROW   (FEAT_DIM / 4)      // 192
#define CHUNKS       96                  // threads per row-slot (each does 2x uint2)
#define ROWS_PER_SLOT 4
#define SLOTS        2
#define ROWS_PER_BLK (ROWS_PER_SLOT * SLOTS)   // 8
#define UNSEEN_F     150.0f

// fp16 copy of z (scratch; __device__ global per allocation rules)
__device__ __align__(16) __half zh_buf[(size_t)BATCH * FEAT_DIM];

// ---- kernel A: one pass over z ----
// thread t handles 8 consecutive floats:
//   - exact f32 copy to output head (streaming stores)
//   - fp16 RN conversion into zh_buf (cached stores; table is reused ~8x)
//   - threads t < TOTAL_ROWS also emit one label element
__global__ void __launch_bounds__(256)
prep_kernel(const float4* __restrict__ z,
            const int*    __restrict__ label_ids,
            float4*       __restrict__ out_head,
            float*        __restrict__ out_labels) {
    const int t = blockIdx.x * blockDim.x + threadIdx.x;  // 0 .. 786431
    float4 v0 = __ldcs(&z[2 * t]);
    float4 v1 = __ldcs(&z[2 * t + 1]);

    // exact copy head
    __stcs(&out_head[2 * t],     v0);
    __stcs(&out_head[2 * t + 1], v1);

    // fp16 table
    __half2 h0 = __floats2half2_rn(v0.x, v0.y);
    __half2 h1 = __floats2half2_rn(v0.z, v0.w);
    __half2 h2 = __floats2half2_rn(v1.x, v1.y);
    __half2 h3 = __floats2half2_rn(v1.z, v1.w);
    uint4 o;
    o.x = *reinterpret_cast<unsigned*>(&h0);
    o.y = *reinterpret_cast<unsigned*>(&h1);
    o.z = *reinterpret_cast<unsigned*>(&h2);
    o.w = *reinterpret_cast<unsigned*>(&h3);
    reinterpret_cast<uint4*>(zh_buf)[t] = o;

    // labels (40960 of them; grid has 786432 threads)
    if (t < TOTAL_ROWS) {
        out_labels[t] = (t < BATCH) ? (float)__ldg(&label_ids[t]) : UNSEEN_F;
    }
}

// ---- kernel B: convex rows only ----
// block = 192 threads = 2 slots x 96 chunk-threads; block covers 8 convex rows.
__global__ void __launch_bounds__(SLOTS * CHUNKS)
convex_kernel(const int*   __restrict__ idx_i,
              const int*   __restrict__ idx_j,
              const float* __restrict__ s,
              float4*      __restrict__ out_convex) {
    const int crow0 = blockIdx.x * ROWS_PER_BLK;
    const int slot  = threadIdx.x / CHUNKS;     // 0..1
    const int c     = threadIdx.x % CHUNKS;     // 0..95
    const int cbase = crow0 + slot * ROWS_PER_SLOT;

    const uint2* __restrict__ zh = (const uint2*)zh_buf;  // 4 halfs per uint2
    const int U2_PER_ROW = FEAT_DIM / 4;                  // 192

    float sw[ROWS_PER_SLOT];
    long  bi[ROWS_PER_SLOT], bj[ROWS_PER_SLOT];
#pragma unroll
    for (int r = 0; r < ROWS_PER_SLOT; r++) {
        const int ci = cbase + r;
        sw[r] = __ldg(&s[ci]);
        bi[r] = (long)__ldg(&idx_i[ci]) * U2_PER_ROW;
        bj[r] = (long)__ldg(&idx_j[ci]) * U2_PER_ROW;
    }
    // 16 independent 8B gather loads in flight
    uint2 a0[ROWS_PER_SLOT], a1[ROWS_PER_SLOT];
    uint2 b0[ROWS_PER_SLOT], b1[ROWS_PER_SLOT];
#pragma unroll
    for (int r = 0; r < ROWS_PER_SLOT; r++) {
        a0[r] = __ldg(&zh[bi[r] + c]);
        a1[r] = __ldg(&zh[bi[r] + CHUNKS + c]);
        b0[r] = __ldg(&zh[bj[r] + c]);
        b1[r] = __ldg(&zh[bj[r] + CHUNKS + c]);
    }
#pragma unroll
    for (int r = 0; r < ROWS_PER_SLOT; r++) {
        const float w = sw[r], ow = 1.0f - sw[r];
        const long obase = (long)(cbase + r) * F4_PER_ROW;

        float2 fa0 = __half22float2(*reinterpret_cast<__half2*>(&a0[r].x));
        float2 fa1 = __half22float2(*reinterpret_cast<__half2*>(&a0[r].y));
        float2 fb0 = __half22float2(*reinterpret_cast<__half2*>(&b0[r].x));
        float2 fb1 = __half22float2(*reinterpret_cast<__half2*>(&b0[r].y));
        float4 o;
        o.x = fmaf(w, fa0.x, ow * fb0.x);
        o.y = fmaf(w, fa0.y, ow * fb0.y);
        o.z = fmaf(w, fa1.x, ow * fb1.x);
        o.w = fmaf(w, fa1.y, ow * fb1.y);
        __stcs(&out_convex[obase + c], o);

        fa0 = __half22float2(*reinterpret_cast<__half2*>(&a1[r].x));
        fa1 = __half22float2(*reinterpret_cast<__half2*>(&a1[r].y));
        fb0 = __half22float2(*reinterpret_cast<__half2*>(&b1[r].x));
        fb1 = __half22float2(*reinterpret_cast<__half2*>(&b1[r].y));
        o.x = fmaf(w, fa0.x, ow * fb0.x);
        o.y = fmaf(w, fa0.y, ow * fb0.y);
        o.z = fmaf(w, fa1.x, ow * fb1.x);
        o.w = fmaf(w, fa1.y, ow * fb1.y);
        __stcs(&out_convex[obase + CHUNKS + c], o);
    }
}

extern "C" void kernel_launch(void* const* d_in, const int* in_sizes, int n_in,
                              void* d_out, int out_size) {
    const float* z         = (const float*)d_in[0];
    const int*   label_ids = (const int*)  d_in[1];
    const int*   idx_i     = (const int*)  d_in[2];
    const int*   idx_j     = (const int*)  d_in[3];
    const float* s         = (const float*)d_in[4];

    float* out        = (float*)d_out;
    float* out_convex = out + (long)BATCH * FEAT_DIM;
    float* out_labels = out + (long)TOTAL_ROWS * FEAT_DIM;

    // A) single pass over z: copy head + fp16 table + labels
    const int n_threads = (BATCH * FEAT_DIM) / 8;   // 786432
    prep_kernel<<<n_threads / 256, 256, 0, 0>>>(
        (const float4*)z, label_ids, (float4*)out, out_labels);

    // B) convex blend
    convex_kernel<<<NUM_CONVEX / ROWS_PER_BLK, SLOTS * CHUNKS, 0, 0>>>(
        idx_i, idx_j, s, (float4*)out_convex);
}

// round 6
// speedup vs baseline: 1.0446x; 1.0446x over previous
#include <cuda_runtime.h>
#include <cuda_fp16.h>
#include <cstdint>

// ConvexSampler R6: R4 structure (convert + fused main) with copy/convex
// block interleaving inside the main kernel for full-duration DRAM/L2 overlap.
// Inputs (metadata order):
//   d_in[0] z         float32 [8192*768]
//   d_in[1] label_ids int32   [8192]
//   d_in[2] idx_i     int32   [32768]
//   d_in[3] idx_j     int32   [32768]
//   d_in[4] s         float32 [32768]
// Output (flattened tuple, float32):
//   [0 .. 40960*768)        z_out (first 8192 rows = z exact copy, next 32768 = convex)
//   [40960*768 .. +40960)   labels (first 8192 = label_ids as float, rest = 150)

#define BATCH        8192
#define FEAT_DIM     768
#define NUM_CONVEX   32768
#define TOTAL_ROWS   (BATCH + NUM_CONVEX)
#define F4_PER_ROW   (FEAT_DIM / 4)      // 192
#define CHUNKS       96                  // threads per row-slot
#define ROWS_PER_SLOT 4
#define SLOTS        2
#define ROWS_PER_BLK (ROWS_PER_SLOT * SLOTS)   // 8
#define COPY_BLOCKS   (BATCH / ROWS_PER_BLK)       // 1024
#define CONVEX_BLOCKS (NUM_CONVEX / ROWS_PER_BLK)  // 4096
#define UNSEEN_F     150.0f

// fp16 copy of z (scratch; __device__ global per allocation rules)
__device__ __align__(16) __half zh_buf[(size_t)BATCH * FEAT_DIM];

// ---- kernel 1: z (f32) -> zh_buf (fp16, RN); 38 MB, short ----
__global__ void __launch_bounds__(256)
convert_kernel(const float4* __restrict__ z) {
    const int t = blockIdx.x * blockDim.x + threadIdx.x;  // 0 .. 786431
    float4 v0 = __ldg(&z[2 * t]);
    float4 v1 = __ldg(&z[2 * t + 1]);
    __half2 h0 = __floats2half2_rn(v0.x, v0.y);
    __half2 h1 = __floats2half2_rn(v0.z, v0.w);
    __half2 h2 = __floats2half2_rn(v1.x, v1.y);
    __half2 h3 = __floats2half2_rn(v1.z, v1.w);
    uint4 o;
    o.x = *reinterpret_cast<unsigned*>(&h0);
    o.y = *reinterpret_cast<unsigned*>(&h1);
    o.z = *reinterpret_cast<unsigned*>(&h2);
    o.w = *reinterpret_cast<unsigned*>(&h3);
    reinterpret_cast<uint4*>(zh_buf)[t] = o;
}

// ---- kernel 2: fused copy + convex blend + labels, interleaved 1:4 ----
__global__ void __launch_bounds__(SLOTS * CHUNKS)
convex_main_kernel(const float4* __restrict__ z,
                   const int*    __restrict__ label_ids,
                   const int*    __restrict__ idx_i,
                   const int*    __restrict__ idx_j,
                   const float*  __restrict__ s,
                   float4*       __restrict__ out_rows,
                   float*        __restrict__ out_labels) {
    const int b = blockIdx.x;            // 0 .. 5119
    const int q = b / 5;
    const bool is_copy = (b % 5 == 0);   // every 5th block copies (1024 total)

    const int slot = threadIdx.x / CHUNKS;     // 0..1
    const int c    = threadIdx.x % CHUNKS;     // 0..95

    if (is_copy) {
        const int row0  = q * ROWS_PER_BLK;            // 0 .. 8184
        const int rbase = row0 + slot * ROWS_PER_SLOT;
        float4 v[ROWS_PER_SLOT][2];
#pragma unroll
        for (int r = 0; r < ROWS_PER_SLOT; r++) {
            const long base = (long)(rbase + r) * F4_PER_ROW;
            v[r][0] = __ldg(&z[base + c]);
            v[r][1] = __ldg(&z[base + CHUNKS + c]);
        }
#pragma unroll
        for (int r = 0; r < ROWS_PER_SLOT; r++) {
            const long base = (long)(rbase + r) * F4_PER_ROW;
            __stcs(&out_rows[base + c], v[r][0]);
            __stcs(&out_rows[base + CHUNKS + c], v[r][1]);
        }
        if (threadIdx.x < ROWS_PER_BLK)
            out_labels[row0 + threadIdx.x] =
                (float)__ldg(&label_ids[row0 + threadIdx.x]);
    } else {
        const int cb    = b - q - 1;                   // convex block id 0..4095
        const int crow0 = cb * ROWS_PER_BLK;           // convex row base
        const int cbase = crow0 + slot * ROWS_PER_SLOT;

        const uint2* __restrict__ zh = (const uint2*)zh_buf;  // 4 halfs per uint2
        const int U2_PER_ROW = FEAT_DIM / 4;                  // 192

        float sw[ROWS_PER_SLOT];
        long  bi[ROWS_PER_SLOT], bj[ROWS_PER_SLOT];
#pragma unroll
        for (int r = 0; r < ROWS_PER_SLOT; r++) {
            const int ci = cbase + r;
            sw[r] = __ldg(&s[ci]);
            bi[r] = (long)__ldg(&idx_i[ci]) * U2_PER_ROW;
            bj[r] = (long)__ldg(&idx_j[ci]) * U2_PER_ROW;
        }
        // 16 independent 8B gather loads in flight
        uint2 a0[ROWS_PER_SLOT], a1[ROWS_PER_SLOT];
        uint2 b0[ROWS_PER_SLOT], b1[ROWS_PER_SLOT];
#pragma unroll
        for (int r = 0; r < ROWS_PER_SLOT; r++) {
            a0[r] = __ldg(&zh[bi[r] + c]);
            a1[r] = __ldg(&zh[bi[r] + CHUNKS + c]);
            b0[r] = __ldg(&zh[bj[r] + c]);
            b1[r] = __ldg(&zh[bj[r] + CHUNKS + c]);
        }
#pragma unroll
        for (int r = 0; r < ROWS_PER_SLOT; r++) {
            const float w = sw[r], ow = 1.0f - sw[r];
            const long obase = (long)(BATCH + cbase + r) * F4_PER_ROW;

            float2 fa0 = __half22float2(*reinterpret_cast<__half2*>(&a0[r].x));
            float2 fa1 = __half22float2(*reinterpret_cast<__half2*>(&a0[r].y));
            float2 fb0 = __half22float2(*reinterpret_cast<__half2*>(&b0[r].x));
            float2 fb1 = __half22float2(*reinterpret_cast<__half2*>(&b0[r].y));
            float4 o;
            o.x = fmaf(w, fa0.x, ow * fb0.x);
            o.y = fmaf(w, fa0.y, ow * fb0.y);
            o.z = fmaf(w, fa1.x, ow * fb1.x);
            o.w = fmaf(w, fa1.y, ow * fb1.y);
            __stcs(&out_rows[obase + c], o);

            fa0 = __half22float2(*reinterpret_cast<__half2*>(&a1[r].x));
            fa1 = __half22float2(*reinterpret_cast<__half2*>(&a1[r].y));
            fb0 = __half22float2(*reinterpret_cast<__half2*>(&b1[r].x));
            fb1 = __half22float2(*reinterpret_cast<__half2*>(&b1[r].y));
            o.x = fmaf(w, fa0.x, ow * fb0.x);
            o.y = fmaf(w, fa0.y, ow * fb0.y);
            o.z = fmaf(w, fa1.x, ow * fb1.x);
            o.w = fmaf(w, fa1.y, ow * fb1.y);
            __stcs(&out_rows[obase + CHUNKS + c], o);
        }
        if (threadIdx.x < ROWS_PER_BLK)
            out_labels[BATCH + crow0 + threadIdx.x] = UNSEEN_F;
    }
}

extern "C" void kernel_launch(void* const* d_in, const int* in_sizes, int n_in,
                              void* d_out, int out_size) {
    const float* z         = (const float*)d_in[0];
    const int*   label_ids = (const int*)  d_in[1];
    const int*   idx_i     = (const int*)  d_in[2];
    const int*   idx_j     = (const int*)  d_in[3];
    const float* s         = (const float*)d_in[4];

    float* out        = (float*)d_out;
    float* out_labels = out + (long)TOTAL_ROWS * FEAT_DIM;

    // 1) build fp16 gather table (also warms z into L2 for the copy branch)
    const int n_cvt = (BATCH * FEAT_DIM) / 8;   // 786432 threads
    convert_kernel<<<n_cvt / 256, 256, 0, 0>>>((const float4*)z);

    // 2) fused copy + blend + labels, copy blocks interleaved 1:4
    convex_main_kernel<<<COPY_BLOCKS + CONVEX_BLOCKS, SLOTS * CHUNKS, 0, 0>>>(
        (const float4*)z, label_ids, idx_i, idx_j, s,
        (float4*)out, out_labels);
}

// round 7
// speedup vs baseline: 1.1241x; 1.0761x over previous
#include <cuda_runtime.h>
#include <cuda_fp16.h>
#include <cstdint>

// ConvexSampler R7: R4 structure + PDL overlap.
//   convert kernel triggers dependent launch at start; main kernel launches
//   programmatically early. Copy blocks (bids 0..1023) run immediately,
//   overlapping with convert; convex blocks griddepcontrol.wait before
//   reading the fp16 table.
// Inputs (metadata order):
//   d_in[0] z         float32 [8192*768]
//   d_in[1] label_ids int32   [8192]
//   d_in[2] idx_i     int32   [32768]
//   d_in[3] idx_j     int32   [32768]
//   d_in[4] s         float32 [32768]
// Output (flattened tuple, float32):
//   [0 .. 40960*768)        z_out (first 8192 rows = z exact copy, next 32768 = convex)
//   [40960*768 .. +40960)   labels (first 8192 = label_ids as float, rest = 150)

#define BATCH        8192
#define FEAT_DIM     768
#define NUM_CONVEX   32768
#define TOTAL_ROWS   (BATCH + NUM_CONVEX)
#define F4_PER_ROW   (FEAT_DIM / 4)      // 192
#define CHUNKS       96                  // threads per row-slot
#define ROWS_PER_SLOT 4
#define SLOTS        2
#define ROWS_PER_BLK (ROWS_PER_SLOT * SLOTS)   // 8
#define UNSEEN_F     150.0f

// fp16 copy of z (scratch; __device__ global per allocation rules)
__device__ __align__(16) __half zh_buf[(size_t)BATCH * FEAT_DIM];

// ---- kernel 1: z (f32) -> zh_buf (fp16, RN) ----
// Fires launch_dependents immediately so the main kernel can begin its
// copy blocks while conversion is still running.
__global__ void __launch_bounds__(256)
convert_kernel(const float4* __restrict__ z) {
    asm volatile("griddepcontrol.launch_dependents;" ::: "memory");
    const int t = blockIdx.x * blockDim.x + threadIdx.x;  // 0 .. 786431
    float4 v0 = __ldg(&z[2 * t]);
    float4 v1 = __ldg(&z[2 * t + 1]);
    __half2 h0 = __floats2half2_rn(v0.x, v0.y);
    __half2 h1 = __floats2half2_rn(v0.z, v0.w);
    __half2 h2 = __floats2half2_rn(v1.x, v1.y);
    __half2 h3 = __floats2half2_rn(v1.z, v1.w);
    uint4 o;
    o.x = *reinterpret_cast<unsigned*>(&h0);
    o.y = *reinterpret_cast<unsigned*>(&h1);
    o.z = *reinterpret_cast<unsigned*>(&h2);
    o.w = *reinterpret_cast<unsigned*>(&h3);
    reinterpret_cast<uint4*>(zh_buf)[t] = o;
}

// ---- kernel 2: fused copy + convex blend + labels (R4 bid layout) ----
__global__ void __launch_bounds__(SLOTS * CHUNKS)
convex_main_kernel(const float4* __restrict__ z,
                   const int*    __restrict__ label_ids,
                   const int*    __restrict__ idx_i,
                   const int*    __restrict__ idx_j,
                   const float*  __restrict__ s,
                   float4*       __restrict__ out_rows,
                   float*        __restrict__ out_labels) {
    const int row0 = blockIdx.x * ROWS_PER_BLK;   // first of 8 rows
    const int slot = threadIdx.x / CHUNKS;        // 0..1
    const int c    = threadIdx.x % CHUNKS;        // 0..95
    const int rbase = row0 + slot * ROWS_PER_SLOT;

    if (row0 < BATCH) {
        // ---- copy blocks: no dependency on the fp16 table; run immediately ----
        float4 v[ROWS_PER_SLOT][2];
#pragma unroll
        for (int r = 0; r < ROWS_PER_SLOT; r++) {
            const long base = (long)(rbase + r) * F4_PER_ROW;
            v[r][0] = __ldg(&z[base + c]);
            v[r][1] = __ldg(&z[base + CHUNKS + c]);
        }
#pragma unroll
        for (int r = 0; r < ROWS_PER_SLOT; r++) {
            const long base = (long)(rbase + r) * F4_PER_ROW;
            __stcs(&out_rows[base + c], v[r][0]);
            __stcs(&out_rows[base + CHUNKS + c], v[r][1]);
        }
        if (threadIdx.x < ROWS_PER_BLK)
            out_labels[row0 + threadIdx.x] =
                (float)__ldg(&label_ids[row0 + threadIdx.x]);
    } else {
        // ---- convex blocks: wait for convert kernel's writes to be visible ----
        asm volatile("griddepcontrol.wait;" ::: "memory");

        const uint2* __restrict__ zh = (const uint2*)zh_buf;  // 4 halfs per uint2
        const int U2_PER_ROW = FEAT_DIM / 4;                  // 192

        float sw[ROWS_PER_SLOT];
        long  bi[ROWS_PER_SLOT], bj[ROWS_PER_SLOT];
#pragma unroll
        for (int r = 0; r < ROWS_PER_SLOT; r++) {
            const int ci = rbase + r - BATCH;
            sw[r] = __ldg(&s[ci]);
            bi[r] = (long)__ldg(&idx_i[ci]) * U2_PER_ROW;
            bj[r] = (long)__ldg(&idx_j[ci]) * U2_PER_ROW;
        }
        // 16 independent 8B gather loads in flight
        uint2 a0[ROWS_PER_SLOT], a1[ROWS_PER_SLOT];
        uint2 b0[ROWS_PER_SLOT], b1[ROWS_PER_SLOT];
#pragma unroll
        for (int r = 0; r < ROWS_PER_SLOT; r++) {
            a0[r] = __ldg(&zh[bi[r] + c]);
            a1[r] = __ldg(&zh[bi[r] + CHUNKS + c]);
            b0[r] = __ldg(&zh[bj[r] + c]);
            b1[r] = __ldg(&zh[bj[r] + CHUNKS + c]);
        }
#pragma unroll
        for (int r = 0; r < ROWS_PER_SLOT; r++) {
            const float w = sw[r], ow = 1.0f - sw[r];
            const long obase = (long)(rbase + r) * F4_PER_ROW;

            float2 fa0 = __half22float2(*reinterpret_cast<__half2*>(&a0[r].x));
            float2 fa1 = __half22float2(*reinterpret_cast<__half2*>(&a0[r].y));
            float2 fb0 = __half22float2(*reinterpret_cast<__half2*>(&b0[r].x));
            float2 fb1 = __half22float2(*reinterpret_cast<__half2*>(&b0[r].y));
            float4 o;
            o.x = fmaf(w, fa0.x, ow * fb0.x);
            o.y = fmaf(w, fa0.y, ow * fb0.y);
            o.z = fmaf(w, fa1.x, ow * fb1.x);
            o.w = fmaf(w, fa1.y, ow * fb1.y);
            __stcs(&out_rows[obase + c], o);

            fa0 = __half22float2(*reinterpret_cast<__half2*>(&a1[r].x));
            fa1 = __half22float2(*reinterpret_cast<__half2*>(&a1[r].y));
            fb0 = __half22float2(*reinterpret_cast<__half2*>(&b1[r].x));
            fb1 = __half22float2(*reinterpret_cast<__half2*>(&b1[r].y));
            o.x = fmaf(w, fa0.x, ow * fb0.x);
            o.y = fmaf(w, fa0.y, ow * fb0.y);
            o.z = fmaf(w, fa1.x, ow * fb1.x);
            o.w = fmaf(w, fa1.y, ow * fb1.y);
            __stcs(&out_rows[obase + CHUNKS + c], o);
        }
        if (threadIdx.x < ROWS_PER_BLK)
            out_labels[row0 + threadIdx.x] = UNSEEN_F;
    }
}

extern "C" void kernel_launch(void* const* d_in, const int* in_sizes, int n_in,
                              void* d_out, int out_size) {
    const float* z         = (const float*)d_in[0];
    const int*   label_ids = (const int*)  d_in[1];
    const int*   idx_i     = (const int*)  d_in[2];
    const int*   idx_j     = (const int*)  d_in[3];
    const float* s         = (const float*)d_in[4];

    float* out        = (float*)d_out;
    float* out_labels = out + (long)TOTAL_ROWS * FEAT_DIM;

    // 1) build fp16 gather table (triggers dependents at start)
    const int n_cvt = (BATCH * FEAT_DIM) / 8;   // 786432 threads
    convert_kernel<<<n_cvt / 256, 256, 0, 0>>>((const float4*)z);

    // 2) fused copy + blend + labels, launched with programmatic dependency
    {
        cudaLaunchConfig_t cfg = {};
        cfg.gridDim  = dim3(TOTAL_ROWS / ROWS_PER_BLK, 1, 1);   // 5120
        cfg.blockDim = dim3(SLOTS * CHUNKS, 1, 1);              // 192
        cfg.dynamicSmemBytes = 0;
        cfg.stream = 0;
        cudaLaunchAttribute attr[1];
        attr[0].id = cudaLaunchAttributeProgrammaticStreamSerialization;
        attr[0].val.programmaticStreamSerializationAllowed = 1;
        cfg.attrs = attr;
        cfg.numAttrs = 1;
        cudaLaunchKernelEx(&cfg, convex_main_kernel,
                           (const float4*)z, label_ids, idx_i, idx_j, s,
                           (float4*)out, out_labels);
    }
}